// round 4
// baseline (speedup 1.0000x reference)
#include <cuda_runtime.h>
#include <cstdint>

#define BB 256
#define TT 100
#define CC 40
#define H1 1024
#define H2 512
#define OO 35
#define MT (BB*TT)

#define NCTA (BB/2)     // 128 CTAs, 2 batches each
#define NTHR 1024

// ---------------- static device scratch ----------------
__device__ float g_P1[(size_t)MT * H1];      // precomputed BN-folded input drive
__device__ float g_Wr1T[H1 * H1];            // [in][out] * scale1[out]
__device__ float g_W2T [H1 * H2];            // [in][out] * scale2[out]
__device__ float g_Wr2T[H2 * H2];            // [in][out] * scale2[out]
__device__ float g_WoT [H2 * OO];            // [in][out]

// ---------------- f32x2 packed helpers ----------------
__device__ __forceinline__ uint64_t pack2(float lo, float hi) {
    uint64_t r;
    asm("mov.b64 %0, {%1, %2};" : "=l"(r) : "r"(__float_as_uint(lo)), "r"(__float_as_uint(hi)));
    return r;
}
__device__ __forceinline__ uint64_t dup2(float v) {
    uint64_t r;
    asm("mov.b64 %0, {%1, %1};" : "=l"(r) : "r"(__float_as_uint(v)));
    return r;
}
__device__ __forceinline__ uint64_t fma2(uint64_t a, uint64_t b, uint64_t c) {
    uint64_t d;
    asm("fma.rn.f32x2 %0, %1, %2, %3;" : "=l"(d) : "l"(a), "l"(b), "l"(c));
    return d;
}
__device__ __forceinline__ uint64_t add2(uint64_t a, uint64_t b) {
    uint64_t d;
    asm("add.rn.f32x2 %0, %1, %2;" : "=l"(d) : "l"(a), "l"(b));
    return d;
}
__device__ __forceinline__ float2 unpack2(uint64_t v) {
    uint32_t lo, hi;
    asm("mov.b64 {%0, %1}, %2;" : "=r"(lo), "=r"(hi) : "l"(v));
    return make_float2(__uint_as_float(lo), __uint_as_float(hi));
}

// ---------------- prep: coalesced tiled transposes with BN scale folding --------------
__global__ void prep_kernel(const float* __restrict__ W_rec1,
                            const float* __restrict__ W2,
                            const float* __restrict__ W_rec2,
                            const float* __restrict__ W_out,
                            const float* __restrict__ g1, const float* __restrict__ v1,
                            const float* __restrict__ g2, const float* __restrict__ v2)
{
    __shared__ float tile[32][33];
    const int z = blockIdx.z;

    const float* src; float* dst; const float* sg; const float* sv;
    int R, Cc;                       // src is [R rows(o)][Cc cols(h)]
    if      (z == 0) { src = W_rec1; dst = g_Wr1T; R = H1; Cc = H1; sg = g1; sv = v1; }
    else if (z == 1) { src = W2;     dst = g_W2T;  R = H2; Cc = H1; sg = g2; sv = v2; }
    else if (z == 2) { src = W_rec2; dst = g_Wr2T; R = H2; Cc = H2; sg = g2; sv = v2; }
    else             { src = W_out;  dst = g_WoT;  R = OO; Cc = H2; sg = nullptr; sv = nullptr; }

    const int x0 = blockIdx.x * 32;  // over cols h
    const int y0 = blockIdx.y * 32;  // over rows o
    if (x0 >= Cc || y0 >= R) return;

    const int tx = threadIdx.x, ty = threadIdx.y;   // (32, 8)

    #pragma unroll
    for (int k = 0; k < 4; k++) {
        int o = y0 + ty + 8*k;
        int h = x0 + tx;
        if (o < R && h < Cc) {
            float sc = sg ? (sg[o] * rsqrtf(sv[o] + 1e-5f)) : 1.0f;
            tile[ty + 8*k][tx] = src[(size_t)o * Cc + h] * sc;
        }
    }
    __syncthreads();
    #pragma unroll
    for (int k = 0; k < 4; k++) {
        int h = x0 + ty + 8*k;
        int o = y0 + tx;
        if (h < Cc && o < R) dst[(size_t)h * R + o] = tile[tx][ty + 8*k];
    }
}

// ---------------- P1 GEMM: 128x128 tile, 256 thr, 8x8/thread, f32x2 packed ------------
__global__ __launch_bounds__(256) void gemm_p1_kernel(
    const float* __restrict__ x,
    const float* __restrict__ W_delay,
    const float* __restrict__ delay_raw,
    const float* __restrict__ g1, const float* __restrict__ b1,
    const float* __restrict__ m1, const float* __restrict__ v1)
{
    __shared__ float xs[CC][128];
    __shared__ float ws[CC][128];
    __shared__ float sc1s[128], sh1s[128];
    __shared__ int   fli[CC];
    __shared__ float frac[CC];

    const int tid = threadIdx.x;
    const int h0  = blockIdx.x * 128;
    const int r0  = blockIdx.y * 128;

    if (tid < CC) {
        float xr = delay_raw[tid];
        float s  = (xr >= 0.0f) ? (1.0f / (1.0f + expf(-xr)))
                                : (expf(xr) / (1.0f + expf(xr)));
        float d  = s * 30.0f;
        float fl = floorf(d);
        fli[tid]  = (int)fl;
        frac[tid] = d - fl;
    }
    if (tid < 128) {
        int hh = h0 + tid;
        float sc = g1[hh] * rsqrtf(v1[hh] + 1e-5f);
        sc1s[tid] = sc;
        sh1s[tid] = b1[hh] - m1[hh] * sc;
    }
    __syncthreads();

    #pragma unroll
    for (int i = tid; i < 128 * CC; i += 256) {
        int j = i / CC, c = i - j * CC;
        ws[c][j] = W_delay[(h0 + j) * CC + c] * sc1s[j];
    }
    #pragma unroll
    for (int i = tid; i < 128 * CC; i += 256) {
        int row = i / CC, c = i - row * CC;
        int r = r0 + row;
        int t = r >> 8;
        int b = r & 255;
        int i0 = t - fli[c];
        float fr = frac[c];
        const float* xb = x + (size_t)b * TT * CC;
        float x0v = (i0 >= 0) ? xb[i0 * CC + c]       : 0.0f;
        float x1v = (i0 >= 1) ? xb[(i0 - 1) * CC + c] : 0.0f;
        xs[c][row] = (1.0f - fr) * x0v + fr * x1v;
    }
    __syncthreads();

    const int ty = tid >> 4;
    const int tx = tid & 15;

    uint64_t acc[8][4];
    #pragma unroll
    for (int i = 0; i < 8; i++)
        #pragma unroll
        for (int j = 0; j < 4; j++) acc[i][j] = 0ULL;

    #pragma unroll
    for (int k = 0; k < CC; k++) {
        float4 A0 = *(const float4*)&xs[k][ty * 8];
        float4 A1 = *(const float4*)&xs[k][ty * 8 + 4];
        float4 W0 = *(const float4*)&ws[k][tx * 8];
        float4 W1 = *(const float4*)&ws[k][tx * 8 + 4];
        uint64_t w01 = pack2(W0.x, W0.y);
        uint64_t w23 = pack2(W0.z, W0.w);
        uint64_t w45 = pack2(W1.x, W1.y);
        uint64_t w67 = pack2(W1.z, W1.w);
        float av[8] = {A0.x, A0.y, A0.z, A0.w, A1.x, A1.y, A1.z, A1.w};
        #pragma unroll
        for (int ii = 0; ii < 8; ii++) {
            uint64_t ad = dup2(av[ii]);
            acc[ii][0] = fma2(ad, w01, acc[ii][0]);
            acc[ii][1] = fma2(ad, w23, acc[ii][1]);
            acc[ii][2] = fma2(ad, w45, acc[ii][2]);
            acc[ii][3] = fma2(ad, w67, acc[ii][3]);
        }
    }

    uint64_t sh0 = pack2(sh1s[tx*8+0], sh1s[tx*8+1]);
    uint64_t sh1 = pack2(sh1s[tx*8+2], sh1s[tx*8+3]);
    uint64_t sh2 = pack2(sh1s[tx*8+4], sh1s[tx*8+5]);
    uint64_t sh3 = pack2(sh1s[tx*8+6], sh1s[tx*8+7]);

    #pragma unroll
    for (int ii = 0; ii < 8; ii++) {
        int r = r0 + ty * 8 + ii;
        float2 p0 = unpack2(add2(acc[ii][0], sh0));
        float2 p1 = unpack2(add2(acc[ii][1], sh1));
        float2 p2 = unpack2(add2(acc[ii][2], sh2));
        float2 p3 = unpack2(add2(acc[ii][3], sh3));
        float4 o0 = make_float4(p0.x, p0.y, p1.x, p1.y);
        float4 o1 = make_float4(p2.x, p2.y, p3.x, p3.y);
        *(float4*)&g_P1[(size_t)r * H1 + h0 + tx * 8]     = o0;
        *(float4*)&g_P1[(size_t)r * H1 + h0 + tx * 8 + 4] = o1;
    }
}

// ---------------- step kernel: 1 sync/step, triple-buffered spike lists ----------------
// Iter t computes: L2(t), L1(t+1), readout(t-1). Prologue computes L1(0).
__global__ __launch_bounds__(NTHR, 1) void snn_kernel(
    const float* __restrict__ bn2_gamma, const float* __restrict__ bn2_beta,
    const float* __restrict__ bn2_mean,  const float* __restrict__ bn2_var,
    const float* __restrict__ alpha1, const float* __restrict__ rho1, const float* __restrict__ beta_a1,
    const float* __restrict__ alpha2, const float* __restrict__ rho2, const float* __restrict__ beta_a2,
    const float* __restrict__ beta_out,
    float* __restrict__ out)
{
    __shared__ int s_list1[3][2][H1];
    __shared__ int s_list2[3][2][H2];
    __shared__ int s_cnt1[3][2];
    __shared__ int s_cnt2[3][2];

    const int tid = threadIdx.x;
    const int b0  = blockIdx.x * 2;

    if (tid < 6) { s_cnt1[tid >> 1][tid & 1] = 0; s_cnt2[tid >> 1][tid & 1] = 0; }

    // layer-1: h = tid, both batches
    const int h = tid;
    const float al1 = alpha1[h], rh1 = rho1[h], ba1 = beta_a1[h];
    float v1a = 0.f, a1a = 0.f, s1a = 0.f;
    float v1b = 0.f, a1b = 0.f, s1b = 0.f;

    // layer-2: bb2 = tid>>9, h2 = tid&511
    const int bb2 = tid >> 9, h2 = tid & (H2 - 1);
    const float sc2    = bn2_gamma[h2] * rsqrtf(bn2_var[h2] + 1e-5f);
    const float shift2 = bn2_beta[h2] - bn2_mean[h2] * sc2;
    const float al2 = alpha2[h2], rh2 = rho2[h2], ba2 = beta_a2[h2];
    float v2 = 0.f, a2 = 0.f, s2 = 0.f;

    // readout (threads 0..69)
    float vo = 0.f, accv = 0.f, bo = 0.f;
    if (tid < 2 * OO) bo = beta_out[tid % OO];

    const size_t hb0 = (size_t)b0 * H1 + h;
    const size_t hb1 = (size_t)(b0 + 1) * H1 + h;

    // P1 software pipeline: p_t1 consumed at iter t for L1(t+1); 2-deep prefetch
    float p0a = g_P1[hb0];                       // P1(0), used in prologue
    float p0b = g_P1[hb1];
    float pA1 = g_P1[(size_t)(1 * BB) * H1 + hb0];   // P1(1) -> iter 0
    float pB1 = g_P1[(size_t)(1 * BB) * H1 + hb1];
    float pA2 = g_P1[(size_t)(2 * BB) * H1 + hb0];   // P1(2) -> iter 1
    float pB2 = g_P1[(size_t)(2 * BB) * H1 + hb1];

    __syncthreads();   // counters zeroed

    // ---- prologue: L1(0), spikes -> buf1[0] ----
    {
        float an = rh1 * a1a + ba1 * s1a;
        float vn = al1 * v1a + (1.0f - al1) * p0a - an - s1a;
        float sn = ((vn - 1.0f) >= 0.0f) ? 1.0f : 0.0f;
        a1a = an; v1a = vn; s1a = sn;
        if (sn != 0.0f) { int pos = atomicAdd(&s_cnt1[0][0], 1); s_list1[0][0][pos] = h; }
    }
    {
        float an = rh1 * a1b + ba1 * s1b;
        float vn = al1 * v1b + (1.0f - al1) * p0b - an - s1b;
        float sn = ((vn - 1.0f) >= 0.0f) ? 1.0f : 0.0f;
        a1b = an; v1b = vn; s1b = sn;
        if (sn != 0.0f) { int pos = atomicAdd(&s_cnt1[0][1], 1); s_list1[0][1][pos] = h; }
    }
    __syncthreads();   // s1(0) visible

    int rq1 = 0;                    // t % 3
    for (int t = 0; t < TT; t++) {
        const int wq1 = (rq1 == 2) ? 0 : rq1 + 1;   // (t+1)%3 : L1(t+1) writes
        const int zq1 = (wq1 == 2) ? 0 : wq1 + 1;   // (t+2)%3 : s1(t-1), free
        const int wq2 = rq1;                        // t%3     : s2(t) writes
        const int rq2 = zq1;                        // (t+2)%3 : s2(t-1)
        const int zq2 = wq1;                        // (t+1)%3 : s2(t-2), free

        if (tid < 2) { s_cnt1[zq1][tid] = 0; s_cnt2[zq2][tid] = 0; }

        // ---- L2(t): reads s1(t), s2(t-1) ----
        {
            float u = shift2;
            int n = s_cnt1[rq1][bb2];
            const int* l1 = s_list1[rq1][bb2];
            for (int j = 0; j < n; j++) u += g_W2T[l1[j] * H2 + h2];
            n = s_cnt2[rq2][bb2];
            const int* l2 = s_list2[rq2][bb2];
            for (int j = 0; j < n; j++) u += g_Wr2T[l2[j] * H2 + h2];

            float an = rh2 * a2 + ba2 * s2;
            float vn = al2 * v2 + (1.0f - al2) * u - an - s2;
            float sn = ((vn - 1.0f) >= 0.0f) ? 1.0f : 0.0f;
            a2 = an; v2 = vn; s2 = sn;
            if (sn != 0.0f) { int pos = atomicAdd(&s_cnt2[wq2][bb2], 1); s_list2[wq2][bb2][pos] = h2; }
        }

        // ---- L1(t+1): reads s1(t), P1(t+1) ----
        if (t + 1 < TT) {
            float reca = 0.f, recb = 0.f;
            int n = s_cnt1[rq1][0];
            const int* lst = s_list1[rq1][0];
            for (int j = 0; j < n; j++) reca += g_Wr1T[lst[j] * H1 + h];
            n = s_cnt1[rq1][1];
            lst = s_list1[rq1][1];
            for (int j = 0; j < n; j++) recb += g_Wr1T[lst[j] * H1 + h];

            {
                float I = pA1 + reca;
                float an = rh1 * a1a + ba1 * s1a;
                float vn = al1 * v1a + (1.0f - al1) * I - an - s1a;
                float sn = ((vn - 1.0f) >= 0.0f) ? 1.0f : 0.0f;
                a1a = an; v1a = vn; s1a = sn;
                if (sn != 0.0f) { int pos = atomicAdd(&s_cnt1[wq1][0], 1); s_list1[wq1][0][pos] = h; }
            }
            {
                float I = pB1 + recb;
                float an = rh1 * a1b + ba1 * s1b;
                float vn = al1 * v1b + (1.0f - al1) * I - an - s1b;
                float sn = ((vn - 1.0f) >= 0.0f) ? 1.0f : 0.0f;
                a1b = an; v1b = vn; s1b = sn;
                if (sn != 0.0f) { int pos = atomicAdd(&s_cnt1[wq1][1], 1); s_list1[wq1][1][pos] = h; }
            }
        }

        // ---- readout(t-1): reads s2(t-1) ----
        if (t >= 1 && tid < 2 * OO) {
            int bb = tid / OO, o = tid - bb * OO;
            float io = 0.f;
            int n = s_cnt2[rq2][bb];
            const int* lst = s_list2[rq2][bb];
            for (int j = 0; j < n; j++) io += g_WoT[lst[j] * OO + o];
            vo = bo * vo + (1.0f - bo) * io;
            accv += vo;
        }

        // ---- prefetch P1(t+3) (consumed at iter t+2) ----
        float pA3 = 0.f, pB3 = 0.f;
        if (t + 3 < TT) {
            pA3 = g_P1[(size_t)((t + 3) * BB) * H1 + hb0];
            pB3 = g_P1[(size_t)((t + 3) * BB) * H1 + hb1];
        }

        __syncthreads();   // the only sync per step

        pA1 = pA2; pB1 = pB2;
        pA2 = pA3; pB2 = pB3;
        rq1 = wq1;
    }

    // ---- epilogue: readout(TT-1), s2(99) in buf2[(TT-1)%3] ----
    if (tid < 2 * OO) {
        int bb = tid / OO, o = tid - bb * OO;
        const int fq = (TT - 1) % 3;
        float io = 0.f;
        int n = s_cnt2[fq][bb];
        const int* lst = s_list2[fq][bb];
        for (int j = 0; j < n; j++) io += g_WoT[lst[j] * OO + o];
        vo = bo * vo + (1.0f - bo) * io;
        accv += vo;
        out[(b0 + bb) * OO + o] = accv * (1.0f / (float)TT);
    }
}

// ---------------- launch ----------------
extern "C" void kernel_launch(void* const* d_in, const int* in_sizes, int n_in,
                              void* d_out, int out_size)
{
    const float* x         = (const float*)d_in[0];
    const float* W_delay   = (const float*)d_in[1];
    const float* delay_raw = (const float*)d_in[2];
    const float* W_rec1    = (const float*)d_in[3];
    const float* W2        = (const float*)d_in[4];
    const float* W_rec2    = (const float*)d_in[5];
    const float* W_out     = (const float*)d_in[6];
    const float* bn1_gamma = (const float*)d_in[7];
    const float* bn1_beta  = (const float*)d_in[8];
    const float* bn1_mean  = (const float*)d_in[9];
    const float* bn1_var   = (const float*)d_in[10];
    const float* bn2_gamma = (const float*)d_in[11];
    const float* bn2_beta  = (const float*)d_in[12];
    const float* bn2_mean  = (const float*)d_in[13];
    const float* bn2_var   = (const float*)d_in[14];
    const float* alpha1    = (const float*)d_in[15];
    const float* rho1      = (const float*)d_in[16];
    const float* beta_a1   = (const float*)d_in[17];
    const float* alpha2    = (const float*)d_in[18];
    const float* rho2      = (const float*)d_in[19];
    const float* beta_a2   = (const float*)d_in[20];
    const float* beta_out  = (const float*)d_in[21];

    dim3 pb(32, 8);
    dim3 pg(32, 32, 4);
    prep_kernel<<<pg, pb>>>(W_rec1, W2, W_rec2, W_out,
                            bn1_gamma, bn1_var, bn2_gamma, bn2_var);

    dim3 gg(H1 / 128, MT / 128);   // (8, 200)
    gemm_p1_kernel<<<gg, 256>>>(x, W_delay, delay_raw,
                                bn1_gamma, bn1_beta, bn1_mean, bn1_var);

    snn_kernel<<<NCTA, NTHR>>>(bn2_gamma, bn2_beta, bn2_mean, bn2_var,
                               alpha1, rho1, beta_a1,
                               alpha2, rho2, beta_a2,
                               beta_out,
                               (float*)d_out);
}

// round 5
// speedup vs baseline: 1.2852x; 1.2852x over previous
#include <cuda_runtime.h>
#include <cstdint>

#define BB 256
#define TT 100
#define CC 40
#define H1 1024
#define H2 512
#define OO 35
#define MT (BB*TT)

#define NCTA (BB/2)     // 128 CTAs, 2 batches each
#define NTHR 1024

// ---------------- static device scratch ----------------
__device__ float g_P1[(size_t)MT * H1];      // BN-folded input drive, layout [b][t][h]
__device__ float g_xdT[(size_t)CC * MT];     // delayed input, transposed [c][r], r=b*TT+t
__device__ float g_WdT[CC * H1];             // (W_delay*sc1)^T : [c][h]
__device__ float g_shift1[H1];
__device__ float g_Wr1T[H1 * H1];            // [in][out] * scale1[out]
__device__ float g_W2T [H1 * H2];            // [in][out] * scale2[out]
__device__ float g_Wr2T[H2 * H2];            // [in][out] * scale2[out]
__device__ float g_WoT [H2 * OO];            // [in][out]

// ---------------- f32x2 packed helpers ----------------
__device__ __forceinline__ uint64_t pack2(float lo, float hi) {
    uint64_t r;
    asm("mov.b64 %0, {%1, %2};" : "=l"(r) : "r"(__float_as_uint(lo)), "r"(__float_as_uint(hi)));
    return r;
}
__device__ __forceinline__ uint64_t dup2(float v) {
    uint64_t r;
    asm("mov.b64 %0, {%1, %1};" : "=l"(r) : "r"(__float_as_uint(v)));
    return r;
}
__device__ __forceinline__ uint64_t fma2(uint64_t a, uint64_t b, uint64_t c) {
    uint64_t d;
    asm("fma.rn.f32x2 %0, %1, %2, %3;" : "=l"(d) : "l"(a), "l"(b), "l"(c));
    return d;
}
__device__ __forceinline__ uint64_t add2(uint64_t a, uint64_t b) {
    uint64_t d;
    asm("add.rn.f32x2 %0, %1, %2;" : "=l"(d) : "l"(a), "l"(b));
    return d;
}
__device__ __forceinline__ float2 unpack2(uint64_t v) {
    uint32_t lo, hi;
    asm("mov.b64 {%0, %1}, %2;" : "=r"(lo), "=r"(hi) : "l"(v));
    return make_float2(__uint_as_float(lo), __uint_as_float(hi));
}

// ---------------- prep: tiled transposes with BN folding + shift1 ---------------------
// z=0: W_rec1 ->Wr1T  z=1: W2 ->W2T  z=2: W_rec2 ->Wr2T  z=3: W_out ->WoT
// z=4: W_delay*sc1 -> g_WdT [c][h]   z=5: g_shift1
__global__ void prep_kernel(const float* __restrict__ W_rec1,
                            const float* __restrict__ W2,
                            const float* __restrict__ W_rec2,
                            const float* __restrict__ W_out,
                            const float* __restrict__ W_delay,
                            const float* __restrict__ g1, const float* __restrict__ b1,
                            const float* __restrict__ m1, const float* __restrict__ v1,
                            const float* __restrict__ g2, const float* __restrict__ v2)
{
    __shared__ float tile[32][33];
    const int z = blockIdx.z;
    const int tx = threadIdx.x, ty = threadIdx.y;   // (32, 8)

    if (z == 5) {
        if (blockIdx.y == 0) {
            int hh = blockIdx.x * 256 + ty * 32 + tx;
            if (hh < H1) {
                float sc = g1[hh] * rsqrtf(v1[hh] + 1e-5f);
                g_shift1[hh] = b1[hh] - m1[hh] * sc;
            }
        }
        return;
    }

    const float* src; float* dst; const float* sg; const float* sv;
    int R, Cc;                       // src is [R rows(o)][Cc cols(h)]
    if      (z == 0) { src = W_rec1;  dst = g_Wr1T; R = H1; Cc = H1; sg = g1; sv = v1; }
    else if (z == 1) { src = W2;      dst = g_W2T;  R = H2; Cc = H1; sg = g2; sv = v2; }
    else if (z == 2) { src = W_rec2;  dst = g_Wr2T; R = H2; Cc = H2; sg = g2; sv = v2; }
    else if (z == 3) { src = W_out;   dst = g_WoT;  R = OO; Cc = H2; sg = nullptr; sv = nullptr; }
    else             { src = W_delay; dst = g_WdT;  R = H1; Cc = CC; sg = g1; sv = v1; }

    const int x0 = blockIdx.x * 32;  // over cols h
    const int y0 = blockIdx.y * 32;  // over rows o
    if (x0 >= Cc || y0 >= R) return;

    #pragma unroll
    for (int k = 0; k < 4; k++) {
        int o = y0 + ty + 8*k;
        int hh = x0 + tx;
        if (o < R && hh < Cc) {
            float sc = sg ? (sg[o] * rsqrtf(sv[o] + 1e-5f)) : 1.0f;
            tile[ty + 8*k][tx] = src[(size_t)o * Cc + hh] * sc;
        }
    }
    __syncthreads();
    #pragma unroll
    for (int k = 0; k < 4; k++) {
        int hh = x0 + ty + 8*k;
        int o = y0 + tx;
        if (hh < Cc && o < R) dst[(size_t)hh * R + o] = tile[tx][ty + 8*k];
    }
}

// ---------------- xd: delayed-input gather, transposed output [c][b*TT+t] -------------
__global__ __launch_bounds__(256) void xd_kernel(const float* __restrict__ x,
                                                 const float* __restrict__ delay_raw)
{
    __shared__ float sx[TT * CC];    // 16 KB: x[b] rows
    __shared__ int   fli[CC];
    __shared__ float frac[CC];

    const int b   = blockIdx.x;
    const int tid = threadIdx.x;

    if (tid < CC) {
        float xr = delay_raw[tid];
        float s  = (xr >= 0.0f) ? (1.0f / (1.0f + expf(-xr)))
                                : (expf(xr) / (1.0f + expf(xr)));
        float d  = s * 30.0f;        // MAX_DELAY
        float fl = floorf(d);
        fli[tid]  = (int)fl;
        frac[tid] = d - fl;
    }
    const float* xb = x + (size_t)b * TT * CC;
    for (int i = tid; i < TT * CC; i += 256) sx[i] = xb[i];
    __syncthreads();

    for (int i = tid; i < TT * CC; i += 256) {
        int c = i / TT, t = i - c * TT;
        int i0 = t - fli[c];
        float fr = frac[c];
        float x0 = (i0 >= 0) ? sx[i0 * CC + c]       : 0.0f;
        float x1 = (i0 >= 1) ? sx[(i0 - 1) * CC + c] : 0.0f;
        g_xdT[(size_t)c * MT + b * TT + t] = (1.0f - fr) * x0 + fr * x1;
    }
}

// ---------------- P1 GEMM: 128x128 tile, coalesced fills, f32x2 mainloop --------------
// P1[r][h] = sum_c xdT[c][r] * WdT[c][h] + shift1[h],  r = b*TT+t
__global__ __launch_bounds__(256) void gemm_p1_kernel()
{
    __shared__ __align__(16) float xs[CC][128];
    __shared__ __align__(16) float ws[CC][128];
    __shared__ float sh1s[128];

    const int tid = threadIdx.x;
    const int h0  = blockIdx.x * 128;
    const int r0  = blockIdx.y * 128;

    // coalesced fills: 1280 float4s each
    #pragma unroll
    for (int v = tid; v < 32 * CC; v += 256) {
        int c = v >> 5, off = v & 31;
        ((float4*)xs)[c * 32 + off] = ((const float4*)(g_xdT + (size_t)c * MT + r0))[off];
    }
    #pragma unroll
    for (int v = tid; v < 32 * CC; v += 256) {
        int c = v >> 5, off = v & 31;
        ((float4*)ws)[c * 32 + off] = ((const float4*)(g_WdT + c * H1 + h0))[off];
    }
    if (tid < 128) sh1s[tid] = g_shift1[h0 + tid];
    __syncthreads();

    const int ty = tid >> 4;
    const int tx = tid & 15;

    uint64_t acc[8][4];
    #pragma unroll
    for (int i = 0; i < 8; i++)
        #pragma unroll
        for (int j = 0; j < 4; j++) acc[i][j] = 0ULL;

    #pragma unroll
    for (int k = 0; k < CC; k++) {
        float4 A0 = *(const float4*)&xs[k][ty * 8];
        float4 A1 = *(const float4*)&xs[k][ty * 8 + 4];
        float4 W0 = *(const float4*)&ws[k][tx * 8];
        float4 W1 = *(const float4*)&ws[k][tx * 8 + 4];
        uint64_t w01 = pack2(W0.x, W0.y);
        uint64_t w23 = pack2(W0.z, W0.w);
        uint64_t w45 = pack2(W1.x, W1.y);
        uint64_t w67 = pack2(W1.z, W1.w);
        float av[8] = {A0.x, A0.y, A0.z, A0.w, A1.x, A1.y, A1.z, A1.w};
        #pragma unroll
        for (int ii = 0; ii < 8; ii++) {
            uint64_t ad = dup2(av[ii]);
            acc[ii][0] = fma2(ad, w01, acc[ii][0]);
            acc[ii][1] = fma2(ad, w23, acc[ii][1]);
            acc[ii][2] = fma2(ad, w45, acc[ii][2]);
            acc[ii][3] = fma2(ad, w67, acc[ii][3]);
        }
    }

    uint64_t sh0 = pack2(sh1s[tx*8+0], sh1s[tx*8+1]);
    uint64_t sh1 = pack2(sh1s[tx*8+2], sh1s[tx*8+3]);
    uint64_t sh2 = pack2(sh1s[tx*8+4], sh1s[tx*8+5]);
    uint64_t sh3 = pack2(sh1s[tx*8+6], sh1s[tx*8+7]);

    #pragma unroll
    for (int ii = 0; ii < 8; ii++) {
        int r = r0 + ty * 8 + ii;
        float2 p0 = unpack2(add2(acc[ii][0], sh0));
        float2 p1 = unpack2(add2(acc[ii][1], sh1));
        float2 p2 = unpack2(add2(acc[ii][2], sh2));
        float2 p3 = unpack2(add2(acc[ii][3], sh3));
        float4 o0 = make_float4(p0.x, p0.y, p1.x, p1.y);
        float4 o1 = make_float4(p2.x, p2.y, p3.x, p3.y);
        *(float4*)&g_P1[(size_t)r * H1 + h0 + tx * 8]     = o0;
        *(float4*)&g_P1[(size_t)r * H1 + h0 + tx * 8 + 4] = o1;
    }
}

// ---------------- step kernel: 1 sync/step, triple-buffered spike lists ----------------
// Iter t computes: L2(t), L1(t+1), readout(t-1). Prologue computes L1(0).
// P1 layout is [b][t][h].
__global__ __launch_bounds__(NTHR, 1) void snn_kernel(
    const float* __restrict__ bn2_gamma, const float* __restrict__ bn2_beta,
    const float* __restrict__ bn2_mean,  const float* __restrict__ bn2_var,
    const float* __restrict__ alpha1, const float* __restrict__ rho1, const float* __restrict__ beta_a1,
    const float* __restrict__ alpha2, const float* __restrict__ rho2, const float* __restrict__ beta_a2,
    const float* __restrict__ beta_out,
    float* __restrict__ out)
{
    __shared__ int s_list1[3][2][H1];
    __shared__ int s_list2[3][2][H2];
    __shared__ int s_cnt1[3][2];
    __shared__ int s_cnt2[3][2];

    const int tid = threadIdx.x;
    const int b0  = blockIdx.x * 2;

    if (tid < 6) { s_cnt1[tid >> 1][tid & 1] = 0; s_cnt2[tid >> 1][tid & 1] = 0; }

    const int h = tid;
    const float al1 = alpha1[h], rh1 = rho1[h], ba1 = beta_a1[h];
    float v1a = 0.f, a1a = 0.f, s1a = 0.f;
    float v1b = 0.f, a1b = 0.f, s1b = 0.f;

    const int bb2 = tid >> 9, h2 = tid & (H2 - 1);
    const float sc2    = bn2_gamma[h2] * rsqrtf(bn2_var[h2] + 1e-5f);
    const float shift2 = bn2_beta[h2] - bn2_mean[h2] * sc2;
    const float al2 = alpha2[h2], rh2 = rho2[h2], ba2 = beta_a2[h2];
    float v2 = 0.f, a2 = 0.f, s2 = 0.f;

    float vo = 0.f, accv = 0.f, bo = 0.f;
    if (tid < 2 * OO) bo = beta_out[tid % OO];

    const size_t hb0 = (size_t)(b0)     * TT * H1 + h;   // [b0][t=0][h]
    const size_t hb1 = (size_t)(b0 + 1) * TT * H1 + h;

    float p0a = g_P1[hb0];
    float p0b = g_P1[hb1];
    float pA1 = g_P1[hb0 + 1 * H1];
    float pB1 = g_P1[hb1 + 1 * H1];
    float pA2 = g_P1[hb0 + 2 * H1];
    float pB2 = g_P1[hb1 + 2 * H1];

    __syncthreads();

    // ---- prologue: L1(0) ----
    {
        float an = rh1 * a1a + ba1 * s1a;
        float vn = al1 * v1a + (1.0f - al1) * p0a - an - s1a;
        float sn = ((vn - 1.0f) >= 0.0f) ? 1.0f : 0.0f;
        a1a = an; v1a = vn; s1a = sn;
        if (sn != 0.0f) { int pos = atomicAdd(&s_cnt1[0][0], 1); s_list1[0][0][pos] = h; }
    }
    {
        float an = rh1 * a1b + ba1 * s1b;
        float vn = al1 * v1b + (1.0f - al1) * p0b - an - s1b;
        float sn = ((vn - 1.0f) >= 0.0f) ? 1.0f : 0.0f;
        a1b = an; v1b = vn; s1b = sn;
        if (sn != 0.0f) { int pos = atomicAdd(&s_cnt1[0][1], 1); s_list1[0][1][pos] = h; }
    }
    __syncthreads();

    int rq1 = 0;
    for (int t = 0; t < TT; t++) {
        const int wq1 = (rq1 == 2) ? 0 : rq1 + 1;
        const int zq1 = (wq1 == 2) ? 0 : wq1 + 1;
        const int wq2 = rq1;
        const int rq2 = zq1;
        const int zq2 = wq1;

        if (tid < 2) { s_cnt1[zq1][tid] = 0; s_cnt2[zq2][tid] = 0; }

        // ---- L2(t) ----
        {
            float u = shift2;
            int n = s_cnt1[rq1][bb2];
            const int* l1 = s_list1[rq1][bb2];
            for (int j = 0; j < n; j++) u += g_W2T[l1[j] * H2 + h2];
            n = s_cnt2[rq2][bb2];
            const int* l2 = s_list2[rq2][bb2];
            for (int j = 0; j < n; j++) u += g_Wr2T[l2[j] * H2 + h2];

            float an = rh2 * a2 + ba2 * s2;
            float vn = al2 * v2 + (1.0f - al2) * u - an - s2;
            float sn = ((vn - 1.0f) >= 0.0f) ? 1.0f : 0.0f;
            a2 = an; v2 = vn; s2 = sn;
            if (sn != 0.0f) { int pos = atomicAdd(&s_cnt2[wq2][bb2], 1); s_list2[wq2][bb2][pos] = h2; }
        }

        // ---- L1(t+1) ----
        if (t + 1 < TT) {
            float reca = 0.f, recb = 0.f;
            int n = s_cnt1[rq1][0];
            const int* lst = s_list1[rq1][0];
            for (int j = 0; j < n; j++) reca += g_Wr1T[lst[j] * H1 + h];
            n = s_cnt1[rq1][1];
            lst = s_list1[rq1][1];
            for (int j = 0; j < n; j++) recb += g_Wr1T[lst[j] * H1 + h];

            {
                float I = pA1 + reca;
                float an = rh1 * a1a + ba1 * s1a;
                float vn = al1 * v1a + (1.0f - al1) * I - an - s1a;
                float sn = ((vn - 1.0f) >= 0.0f) ? 1.0f : 0.0f;
                a1a = an; v1a = vn; s1a = sn;
                if (sn != 0.0f) { int pos = atomicAdd(&s_cnt1[wq1][0], 1); s_list1[wq1][0][pos] = h; }
            }
            {
                float I = pB1 + recb;
                float an = rh1 * a1b + ba1 * s1b;
                float vn = al1 * v1b + (1.0f - al1) * I - an - s1b;
                float sn = ((vn - 1.0f) >= 0.0f) ? 1.0f : 0.0f;
                a1b = an; v1b = vn; s1b = sn;
                if (sn != 0.0f) { int pos = atomicAdd(&s_cnt1[wq1][1], 1); s_list1[wq1][1][pos] = h; }
            }
        }

        // ---- readout(t-1) ----
        if (t >= 1 && tid < 2 * OO) {
            int bb = tid / OO, o = tid - bb * OO;
            float io = 0.f;
            int n = s_cnt2[rq2][bb];
            const int* lst = s_list2[rq2][bb];
            for (int j = 0; j < n; j++) io += g_WoT[lst[j] * OO + o];
            vo = bo * vo + (1.0f - bo) * io;
            accv += vo;
        }

        // ---- prefetch P1(t+3) ----
        float pA3 = 0.f, pB3 = 0.f;
        if (t + 3 < TT) {
            pA3 = g_P1[hb0 + (size_t)(t + 3) * H1];
            pB3 = g_P1[hb1 + (size_t)(t + 3) * H1];
        }

        __syncthreads();

        pA1 = pA2; pB1 = pB2;
        pA2 = pA3; pB2 = pB3;
        rq1 = wq1;
    }

    if (tid < 2 * OO) {
        int bb = tid / OO, o = tid - bb * OO;
        const int fq = (TT - 1) % 3;
        float io = 0.f;
        int n = s_cnt2[fq][bb];
        const int* lst = s_list2[fq][bb];
        for (int j = 0; j < n; j++) io += g_WoT[lst[j] * OO + o];
        vo = bo * vo + (1.0f - bo) * io;
        accv += vo;
        out[(b0 + bb) * OO + o] = accv * (1.0f / (float)TT);
    }
}

// ---------------- launch ----------------
extern "C" void kernel_launch(void* const* d_in, const int* in_sizes, int n_in,
                              void* d_out, int out_size)
{
    const float* x         = (const float*)d_in[0];
    const float* W_delay   = (const float*)d_in[1];
    const float* delay_raw = (const float*)d_in[2];
    const float* W_rec1    = (const float*)d_in[3];
    const float* W2        = (const float*)d_in[4];
    const float* W_rec2    = (const float*)d_in[5];
    const float* W_out     = (const float*)d_in[6];
    const float* bn1_gamma = (const float*)d_in[7];
    const float* bn1_beta  = (const float*)d_in[8];
    const float* bn1_mean  = (const float*)d_in[9];
    const float* bn1_var   = (const float*)d_in[10];
    const float* bn2_gamma = (const float*)d_in[11];
    const float* bn2_beta  = (const float*)d_in[12];
    const float* bn2_mean  = (const float*)d_in[13];
    const float* bn2_var   = (const float*)d_in[14];
    const float* alpha1    = (const float*)d_in[15];
    const float* rho1      = (const float*)d_in[16];
    const float* beta_a1   = (const float*)d_in[17];
    const float* alpha2    = (const float*)d_in[18];
    const float* rho2      = (const float*)d_in[19];
    const float* beta_a2   = (const float*)d_in[20];
    const float* beta_out  = (const float*)d_in[21];

    dim3 pb(32, 8);
    dim3 pg(32, 32, 6);
    prep_kernel<<<pg, pb>>>(W_rec1, W2, W_rec2, W_out, W_delay,
                            bn1_gamma, bn1_beta, bn1_mean, bn1_var,
                            bn2_gamma, bn2_var);

    xd_kernel<<<BB, 256>>>(x, delay_raw);

    dim3 gg(H1 / 128, MT / 128);   // (8, 200)
    gemm_p1_kernel<<<gg, 256>>>();

    snn_kernel<<<NCTA, NTHR>>>(bn2_gamma, bn2_beta, bn2_mean, bn2_var,
                               alpha1, rho1, beta_a1,
                               alpha2, rho2, beta_a2,
                               beta_out,
                               (float*)d_out);
}

// round 6
// speedup vs baseline: 1.5936x; 1.2400x over previous
#include <cuda_runtime.h>
#include <cstdint>

#define BB 256
#define TT 100
#define CC 40
#define H1 1024
#define H2 512
#define OO 35
#define MT (BB*TT)

// ---------------- static device scratch ----------------
__device__ float g_P1[(size_t)(MT + 3) * H1];  // (1-al1)-scaled input drive, [b][t][h], +3 steps pad
__device__ float g_xdT[(size_t)CC * MT];       // delayed input, transposed [c][r], r=b*TT+t
__device__ float g_WdT[CC * H1];               // (W_delay*sc1)^T : [c][h]
__device__ float g_shift1[H1];
__device__ float g_Wr1T[H1 * H1];              // [in][out] * sc1[out]*(1-al1[out])
__device__ float g_W2T [H1 * H2];              // [in][out] * sc2[out]*(1-al2[out])
__device__ float g_Wr2T[H2 * H2];              // [in][out] * sc2[out]*(1-al2[out])
__device__ float g_WoT [H2 * OO];              // [in][out] * (1-beta_out[out])

// ---------------- f32x2 packed helpers ----------------
__device__ __forceinline__ uint64_t pack2(float lo, float hi) {
    uint64_t r;
    asm("mov.b64 %0, {%1, %2};" : "=l"(r) : "r"(__float_as_uint(lo)), "r"(__float_as_uint(hi)));
    return r;
}
__device__ __forceinline__ uint64_t dup2(float v) {
    uint64_t r;
    asm("mov.b64 %0, {%1, %1};" : "=l"(r) : "r"(__float_as_uint(v)));
    return r;
}
__device__ __forceinline__ uint64_t fma2(uint64_t a, uint64_t b, uint64_t c) {
    uint64_t d;
    asm("fma.rn.f32x2 %0, %1, %2, %3;" : "=l"(d) : "l"(a), "l"(b), "l"(c));
    return d;
}
__device__ __forceinline__ uint64_t add2(uint64_t a, uint64_t b) {
    uint64_t d;
    asm("add.rn.f32x2 %0, %1, %2;" : "=l"(d) : "l"(a), "l"(b));
    return d;
}
__device__ __forceinline__ float2 unpack2(uint64_t v) {
    uint32_t lo, hi;
    asm("mov.b64 {%0, %1}, %2;" : "=r"(lo), "=r"(hi) : "l"(v));
    return make_float2(__uint_as_float(lo), __uint_as_float(hi));
}

// ---------------- prep: tiled transposes, scale folded (incl. (1-alpha)), smem-staged sc
__global__ void prep_kernel(const float* __restrict__ W_rec1,
                            const float* __restrict__ W2,
                            const float* __restrict__ W_rec2,
                            const float* __restrict__ W_out,
                            const float* __restrict__ W_delay,
                            const float* __restrict__ g1, const float* __restrict__ b1,
                            const float* __restrict__ m1, const float* __restrict__ v1,
                            const float* __restrict__ g2, const float* __restrict__ v2,
                            const float* __restrict__ alpha1, const float* __restrict__ alpha2,
                            const float* __restrict__ beta_out)
{
    __shared__ float tile[32][33];
    __shared__ float scs[32];
    const int z = blockIdx.z;
    const int tx = threadIdx.x, ty = threadIdx.y;   // (32, 8)

    if (z == 5) {
        if (blockIdx.y == 0) {
            int hh = blockIdx.x * 256 + ty * 32 + tx;
            if (hh < H1) {
                float sc = g1[hh] * rsqrtf(v1[hh] + 1e-5f);
                g_shift1[hh] = b1[hh] - m1[hh] * sc;
            }
        }
        return;
    }

    const float* src; float* dst;
    int R, Cc;                       // src is [R rows(o)][Cc cols(h)]
    if      (z == 0) { src = W_rec1;  dst = g_Wr1T; R = H1; Cc = H1; }
    else if (z == 1) { src = W2;      dst = g_W2T;  R = H2; Cc = H1; }
    else if (z == 2) { src = W_rec2;  dst = g_Wr2T; R = H2; Cc = H2; }
    else if (z == 3) { src = W_out;   dst = g_WoT;  R = OO; Cc = H2; }
    else             { src = W_delay; dst = g_WdT;  R = H1; Cc = CC; }

    const int x0 = blockIdx.x * 32;  // over cols h
    const int y0 = blockIdx.y * 32;  // over rows o
    if (x0 >= Cc || y0 >= R) return;

    if (ty == 0) {
        int o = y0 + tx;
        float sc = 1.0f;
        if (o < R) {
            if (z == 0)                 sc = g1[o] * rsqrtf(v1[o] + 1e-5f) * (1.0f - alpha1[o]);
            else if (z == 1 || z == 2)  sc = g2[o] * rsqrtf(v2[o] + 1e-5f) * (1.0f - alpha2[o]);
            else if (z == 3)            sc = 1.0f - beta_out[o];
            else                        sc = g1[o] * rsqrtf(v1[o] + 1e-5f);
        }
        scs[tx] = sc;
    }
    __syncthreads();

    #pragma unroll
    for (int k = 0; k < 4; k++) {
        int o = y0 + ty + 8*k;
        int hh = x0 + tx;
        if (o < R && hh < Cc)
            tile[ty + 8*k][tx] = src[(size_t)o * Cc + hh] * scs[ty + 8*k];
    }
    __syncthreads();
    #pragma unroll
    for (int k = 0; k < 4; k++) {
        int hh = x0 + ty + 8*k;
        int o = y0 + tx;
        if (hh < Cc && o < R) dst[(size_t)hh * R + o] = tile[tx][ty + 8*k];
    }
}

// ---------------- xd: delayed-input gather, transposed output [c][b*TT+t] -------------
__global__ __launch_bounds__(256) void xd_kernel(const float* __restrict__ x,
                                                 const float* __restrict__ delay_raw)
{
    __shared__ float sx[TT * CC];
    __shared__ int   fli[CC];
    __shared__ float frac[CC];

    const int b   = blockIdx.x;
    const int tid = threadIdx.x;

    if (tid < CC) {
        float xr = delay_raw[tid];
        float s  = (xr >= 0.0f) ? (1.0f / (1.0f + expf(-xr)))
                                : (expf(xr) / (1.0f + expf(xr)));
        float d  = s * 30.0f;        // MAX_DELAY
        float fl = floorf(d);
        fli[tid]  = (int)fl;
        frac[tid] = d - fl;
    }
    const float* xb = x + (size_t)b * TT * CC;
    for (int i = tid; i < TT * CC; i += 256) sx[i] = xb[i];
    __syncthreads();

    for (int i = tid; i < TT * CC; i += 256) {
        int c = i / TT, t = i - c * TT;
        int i0 = t - fli[c];
        float fr = frac[c];
        float x0 = (i0 >= 0) ? sx[i0 * CC + c]       : 0.0f;
        float x1 = (i0 >= 1) ? sx[(i0 - 1) * CC + c] : 0.0f;
        g_xdT[(size_t)c * MT + b * TT + t] = (1.0f - fr) * x0 + fr * x1;
    }
}

// ---------------- P1 GEMM: 128x128, f32x2 mainloop, (1-al1)-scaled epilogue -----------
__global__ __launch_bounds__(256) void gemm_p1_kernel(const float* __restrict__ alpha1)
{
    __shared__ __align__(16) float xs[CC][128];
    __shared__ __align__(16) float ws[CC][128];
    __shared__ float sh1s[128];
    __shared__ float omas[128];

    const int tid = threadIdx.x;
    const int h0  = blockIdx.x * 128;
    const int r0  = blockIdx.y * 128;

    #pragma unroll
    for (int v = tid; v < 32 * CC; v += 256) {
        int c = v >> 5, off = v & 31;
        ((float4*)xs)[c * 32 + off] = ((const float4*)(g_xdT + (size_t)c * MT + r0))[off];
    }
    #pragma unroll
    for (int v = tid; v < 32 * CC; v += 256) {
        int c = v >> 5, off = v & 31;
        ((float4*)ws)[c * 32 + off] = ((const float4*)(g_WdT + c * H1 + h0))[off];
    }
    if (tid < 128) {
        sh1s[tid] = g_shift1[h0 + tid];
        omas[tid] = 1.0f - alpha1[h0 + tid];
    }
    __syncthreads();

    const int ty = tid >> 4;
    const int tx = tid & 15;

    uint64_t acc[8][4];
    #pragma unroll
    for (int i = 0; i < 8; i++)
        #pragma unroll
        for (int j = 0; j < 4; j++) acc[i][j] = 0ULL;

    #pragma unroll
    for (int k = 0; k < CC; k++) {
        float4 A0 = *(const float4*)&xs[k][ty * 8];
        float4 A1 = *(const float4*)&xs[k][ty * 8 + 4];
        float4 W0 = *(const float4*)&ws[k][tx * 8];
        float4 W1 = *(const float4*)&ws[k][tx * 8 + 4];
        uint64_t w01 = pack2(W0.x, W0.y);
        uint64_t w23 = pack2(W0.z, W0.w);
        uint64_t w45 = pack2(W1.x, W1.y);
        uint64_t w67 = pack2(W1.z, W1.w);
        float av[8] = {A0.x, A0.y, A0.z, A0.w, A1.x, A1.y, A1.z, A1.w};
        #pragma unroll
        for (int ii = 0; ii < 8; ii++) {
            uint64_t ad = dup2(av[ii]);
            acc[ii][0] = fma2(ad, w01, acc[ii][0]);
            acc[ii][1] = fma2(ad, w23, acc[ii][1]);
            acc[ii][2] = fma2(ad, w45, acc[ii][2]);
            acc[ii][3] = fma2(ad, w67, acc[ii][3]);
        }
    }

    uint64_t sh0 = pack2(sh1s[tx*8+0], sh1s[tx*8+1]);
    uint64_t sh1 = pack2(sh1s[tx*8+2], sh1s[tx*8+3]);
    uint64_t sh2 = pack2(sh1s[tx*8+4], sh1s[tx*8+5]);
    uint64_t sh3 = pack2(sh1s[tx*8+6], sh1s[tx*8+7]);
    float om[8];
    #pragma unroll
    for (int j = 0; j < 8; j++) om[j] = omas[tx*8+j];

    #pragma unroll
    for (int ii = 0; ii < 8; ii++) {
        int r = r0 + ty * 8 + ii;
        float2 p0 = unpack2(add2(acc[ii][0], sh0));
        float2 p1 = unpack2(add2(acc[ii][1], sh1));
        float2 p2 = unpack2(add2(acc[ii][2], sh2));
        float2 p3 = unpack2(add2(acc[ii][3], sh3));
        float4 o0 = make_float4(p0.x*om[0], p0.y*om[1], p1.x*om[2], p1.y*om[3]);
        float4 o1 = make_float4(p2.x*om[4], p2.y*om[5], p3.x*om[6], p3.y*om[7]);
        *(float4*)&g_P1[(size_t)r * H1 + h0 + tx * 8]     = o0;
        *(float4*)&g_P1[(size_t)r * H1 + h0 + tx * 8 + 4] = o1;
    }
}

// ---------------- step kernel: 256 CTAs x 512 thr, mod-3 unrolled, constant indices ----
#define SNN_STEP(RQ1, WQ1, ZQ1, DO_L1, DO_RO)                                              \
{                                                                                          \
    if (tid == 0) { s_cnt1[ZQ1] = 0; s_cnt2[WQ1] = 0; }                                    \
    /* L2(t): reads s1(t) buf RQ1, s2(t-1) buf ZQ1; writes s2(t) buf RQ1 */                \
    {                                                                                      \
        float u = shift2s;                                                                 \
        int n = s_cnt1[RQ1];                                                               \
        for (int j = 0; j < n; j++) u += g_W2T[s_list1[RQ1][j] * H2 + tid];                \
        int m = s_cnt2[ZQ1];                                                               \
        for (int j = 0; j < m; j++) u += g_Wr2T[s_list2[ZQ1][j] * H2 + tid];               \
        float an = rh2 * a2 + ba2 * s2;                                                    \
        float vn = al2 * v2 + u - an - s2;                                                 \
        float sn = (vn >= 1.0f) ? 1.0f : 0.0f;                                             \
        a2 = an; v2 = vn; s2 = sn;                                                         \
        if (sn != 0.0f) { int pos = atomicAdd(&s_cnt2[RQ1], 1); s_list2[RQ1][pos] = tid; } \
    }                                                                                      \
    /* L1(t+1): reads s1(t) buf RQ1, P1s(t+1); writes buf WQ1 */                           \
    if (DO_L1) {                                                                           \
        float r0 = 0.f, r1 = 0.f;                                                          \
        int n = s_cnt1[RQ1];                                                               \
        for (int j = 0; j < n; j++) {                                                      \
            const float* row = g_Wr1T + s_list1[RQ1][j] * H1 + tid;                        \
            r0 += row[0]; r1 += row[512];                                                  \
        }                                                                                  \
        {                                                                                  \
            float an = rh1_0 * a1_0 + ba1_0 * s1_0;                                        \
            float vn = al1_0 * v1_0 + p1n0 + r0 - an - s1_0;                               \
            float sn = (vn >= 1.0f) ? 1.0f : 0.0f;                                         \
            a1_0 = an; v1_0 = vn; s1_0 = sn;                                               \
            if (sn != 0.0f) { int pos = atomicAdd(&s_cnt1[WQ1], 1); s_list1[WQ1][pos] = tid; } \
        }                                                                                  \
        {                                                                                  \
            float an = rh1_1 * a1_1 + ba1_1 * s1_1;                                        \
            float vn = al1_1 * v1_1 + p1n1 + r1 - an - s1_1;                               \
            float sn = (vn >= 1.0f) ? 1.0f : 0.0f;                                         \
            a1_1 = an; v1_1 = vn; s1_1 = sn;                                               \
            if (sn != 0.0f) { int pos = atomicAdd(&s_cnt1[WQ1], 1); s_list1[WQ1][pos] = tid + 512; } \
        }                                                                                  \
    }                                                                                      \
    /* readout(t-1): reads s2(t-1) buf ZQ1 */                                              \
    if (DO_RO && tid < OO) {                                                               \
        float io = 0.f;                                                                    \
        int m = s_cnt2[ZQ1];                                                               \
        for (int j = 0; j < m; j++) io += g_WoT[s_list2[ZQ1][j] * OO + tid];               \
        vo = bo * vo + io; accv += vo;                                                     \
    }                                                                                      \
    { float q0 = pf[0], q1 = pf[512]; pf += H1;                                            \
      __syncthreads();                                                                     \
      p1n0 = p2n0; p1n1 = p2n1; p2n0 = q0; p2n1 = q1; }                                    \
}

__global__ __launch_bounds__(512, 2) void snn_kernel(
    const float* __restrict__ bn2_gamma, const float* __restrict__ bn2_beta,
    const float* __restrict__ bn2_mean,  const float* __restrict__ bn2_var,
    const float* __restrict__ alpha1, const float* __restrict__ rho1, const float* __restrict__ beta_a1,
    const float* __restrict__ alpha2, const float* __restrict__ rho2, const float* __restrict__ beta_a2,
    const float* __restrict__ beta_out,
    float* __restrict__ out)
{
    __shared__ int s_list1[3][H1];
    __shared__ int s_list2[3][H2];
    __shared__ int s_cnt1[3];
    __shared__ int s_cnt2[3];

    const int tid = threadIdx.x;
    const int b   = blockIdx.x;

    if (tid < 3) { s_cnt1[tid] = 0; s_cnt2[tid] = 0; }

    // layer-1: neurons tid and tid+512
    const float al1_0 = alpha1[tid],       rh1_0 = rho1[tid],       ba1_0 = beta_a1[tid];
    const float al1_1 = alpha1[tid + 512], rh1_1 = rho1[tid + 512], ba1_1 = beta_a1[tid + 512];
    float v1_0 = 0.f, a1_0 = 0.f, s1_0 = 0.f;
    float v1_1 = 0.f, a1_1 = 0.f, s1_1 = 0.f;

    // layer-2: neuron tid (H2 = 512)
    const float sc2     = bn2_gamma[tid & (H2-1)] * rsqrtf(bn2_var[tid & (H2-1)] + 1e-5f);
    const float al2     = alpha2[tid & (H2-1)];
    const float shift2s = (1.0f - al2) * (bn2_beta[tid & (H2-1)] - bn2_mean[tid & (H2-1)] * sc2);
    const float rh2 = rho2[tid & (H2-1)], ba2 = beta_a2[tid & (H2-1)];
    float v2 = 0.f, a2 = 0.f, s2 = 0.f;

    // readout (threads 0..34)
    float vo = 0.f, accv = 0.f, bo = 0.f;
    if (tid < OO) bo = beta_out[tid];

    const float* base = g_P1 + (size_t)b * TT * H1 + tid;
    float p0n0 = base[0],      p0n1 = base[512];
    float p1n0 = base[H1],     p1n1 = base[H1 + 512];
    float p2n0 = base[2*H1],   p2n1 = base[2*H1 + 512];
    const float* pf = base + 3 * H1;

    __syncthreads();

    // ---- prologue: L1(0) -> buf 0 ----
    {
        float an = rh1_0 * a1_0 + ba1_0 * s1_0;
        float vn = al1_0 * v1_0 + p0n0 - an - s1_0;
        float sn = (vn >= 1.0f) ? 1.0f : 0.0f;
        a1_0 = an; v1_0 = vn; s1_0 = sn;
        if (sn != 0.0f) { int pos = atomicAdd(&s_cnt1[0], 1); s_list1[0][pos] = tid; }
    }
    {
        float an = rh1_1 * a1_1 + ba1_1 * s1_1;
        float vn = al1_1 * v1_1 + p0n1 - an - s1_1;
        float sn = (vn >= 1.0f) ? 1.0f : 0.0f;
        a1_1 = an; v1_1 = vn; s1_1 = sn;
        if (sn != 0.0f) { int pos = atomicAdd(&s_cnt1[0], 1); s_list1[0][pos] = tid + 512; }
    }
    __syncthreads();

    // iter 0 (no readout), then 32 triples covering t=1..96, then t=97,98,99
    SNN_STEP(0, 1, 2, 1, 0)
    #pragma unroll 1
    for (int k = 0; k < 32; k++) {
        SNN_STEP(1, 2, 0, 1, 1)
        SNN_STEP(2, 0, 1, 1, 1)
        SNN_STEP(0, 1, 2, 1, 1)
    }
    SNN_STEP(1, 2, 0, 1, 1)     // t=97
    SNN_STEP(2, 0, 1, 1, 1)     // t=98
    SNN_STEP(0, 1, 2, 0, 1)     // t=99, no L1(100)

    // ---- epilogue: readout(99), s2(99) in buf 0 ----
    if (tid < OO) {
        float io = 0.f;
        int m = s_cnt2[0];
        for (int j = 0; j < m; j++) io += g_WoT[s_list2[0][j] * OO + tid];
        vo = bo * vo + io;
        accv += vo;
        out[b * OO + tid] = accv * (1.0f / (float)TT);
    }
}

// ---------------- launch ----------------
extern "C" void kernel_launch(void* const* d_in, const int* in_sizes, int n_in,
                              void* d_out, int out_size)
{
    const float* x         = (const float*)d_in[0];
    const float* W_delay   = (const float*)d_in[1];
    const float* delay_raw = (const float*)d_in[2];
    const float* W_rec1    = (const float*)d_in[3];
    const float* W2        = (const float*)d_in[4];
    const float* W_rec2    = (const float*)d_in[5];
    const float* W_out     = (const float*)d_in[6];
    const float* bn1_gamma = (const float*)d_in[7];
    const float* bn1_beta  = (const float*)d_in[8];
    const float* bn1_mean  = (const float*)d_in[9];
    const float* bn1_var   = (const float*)d_in[10];
    const float* bn2_gamma = (const float*)d_in[11];
    const float* bn2_beta  = (const float*)d_in[12];
    const float* bn2_mean  = (const float*)d_in[13];
    const float* bn2_var   = (const float*)d_in[14];
    const float* alpha1    = (const float*)d_in[15];
    const float* rho1      = (const float*)d_in[16];
    const float* beta_a1   = (const float*)d_in[17];
    const float* alpha2    = (const float*)d_in[18];
    const float* rho2      = (const float*)d_in[19];
    const float* beta_a2   = (const float*)d_in[20];
    const float* beta_out  = (const float*)d_in[21];

    dim3 pb(32, 8);
    dim3 pg(32, 32, 6);
    prep_kernel<<<pg, pb>>>(W_rec1, W2, W_rec2, W_out, W_delay,
                            bn1_gamma, bn1_beta, bn1_mean, bn1_var,
                            bn2_gamma, bn2_var,
                            alpha1, alpha2, beta_out);

    xd_kernel<<<BB, 256>>>(x, delay_raw);

    dim3 gg(H1 / 128, MT / 128);   // (8, 200)
    gemm_p1_kernel<<<gg, 256>>>(alpha1);

    snn_kernel<<<BB, 512>>>(bn2_gamma, bn2_beta, bn2_mean, bn2_var,
                            alpha1, rho1, beta_a1,
                            alpha2, rho2, beta_a2,
                            beta_out,
                            (float*)d_out);
}

// round 7
// speedup vs baseline: 2.0527x; 1.2881x over previous
#include <cuda_runtime.h>
#include <cuda_bf16.h>
#include <cstdint>

#define BB 256
#define TT 100
#define CC 40
#define H1 1024
#define H2 512
#define OO 35
#define MT (BB*TT)

// ---------------- static device scratch ----------------
__device__ __nv_bfloat162 g_P1h[(size_t)(MT + 4) * (H1/2)];  // (1-al1)-scaled drive, [b][t][pair], bf16x2
__device__ float g_xdT[(size_t)CC * MT];       // delayed input, transposed [c][r], r=b*TT+t
__device__ float g_WdT[CC * H1];               // (W_delay*sc1)^T : [c][h]
__device__ float g_shift1[H1];
__device__ float g_Wr1T[H1 * H1];              // [in][out] * sc1[out]*(1-al1[out])
__device__ float g_W2T [H1 * H2];              // [in][out] * sc2[out]*(1-al2[out])
__device__ float g_Wr2T[H2 * H2];              // [in][out] * sc2[out]*(1-al2[out])
__device__ float g_WoT [H2 * OO];              // [in][out] * (1-beta_out[out])

// ---------------- f32x2 packed helpers ----------------
__device__ __forceinline__ uint64_t pack2(float lo, float hi) {
    uint64_t r;
    asm("mov.b64 %0, {%1, %2};" : "=l"(r) : "r"(__float_as_uint(lo)), "r"(__float_as_uint(hi)));
    return r;
}
__device__ __forceinline__ uint64_t dup2(float v) {
    uint64_t r;
    asm("mov.b64 %0, {%1, %1};" : "=l"(r) : "r"(__float_as_uint(v)));
    return r;
}
__device__ __forceinline__ uint64_t fma2(uint64_t a, uint64_t b, uint64_t c) {
    uint64_t d;
    asm("fma.rn.f32x2 %0, %1, %2, %3;" : "=l"(d) : "l"(a), "l"(b), "l"(c));
    return d;
}
__device__ __forceinline__ uint64_t add2(uint64_t a, uint64_t b) {
    uint64_t d;
    asm("add.rn.f32x2 %0, %1, %2;" : "=l"(d) : "l"(a), "l"(b));
    return d;
}
__device__ __forceinline__ float2 unpack2(uint64_t v) {
    uint32_t lo, hi;
    asm("mov.b64 {%0, %1}, %2;" : "=r"(lo), "=r"(hi) : "l"(v));
    return make_float2(__uint_as_float(lo), __uint_as_float(hi));
}

// ---------------- prep: tiled transposes, scale folded (incl. (1-alpha)) --------------
__global__ void prep_kernel(const float* __restrict__ W_rec1,
                            const float* __restrict__ W2,
                            const float* __restrict__ W_rec2,
                            const float* __restrict__ W_out,
                            const float* __restrict__ W_delay,
                            const float* __restrict__ g1, const float* __restrict__ b1,
                            const float* __restrict__ m1, const float* __restrict__ v1,
                            const float* __restrict__ g2, const float* __restrict__ v2,
                            const float* __restrict__ alpha1, const float* __restrict__ alpha2,
                            const float* __restrict__ beta_out)
{
    __shared__ float tile[32][33];
    __shared__ float scs[32];
    const int z = blockIdx.z;
    const int tx = threadIdx.x, ty = threadIdx.y;   // (32, 8)

    if (z == 5) {
        if (blockIdx.y == 0) {
            int hh = blockIdx.x * 256 + ty * 32 + tx;
            if (hh < H1) {
                float sc = g1[hh] * rsqrtf(v1[hh] + 1e-5f);
                g_shift1[hh] = b1[hh] - m1[hh] * sc;
            }
        }
        return;
    }

    const float* src; float* dst;
    int R, Cc;                       // src is [R rows(o)][Cc cols(h)]
    if      (z == 0) { src = W_rec1;  dst = g_Wr1T; R = H1; Cc = H1; }
    else if (z == 1) { src = W2;      dst = g_W2T;  R = H2; Cc = H1; }
    else if (z == 2) { src = W_rec2;  dst = g_Wr2T; R = H2; Cc = H2; }
    else if (z == 3) { src = W_out;   dst = g_WoT;  R = OO; Cc = H2; }
    else             { src = W_delay; dst = g_WdT;  R = H1; Cc = CC; }

    const int x0 = blockIdx.x * 32;  // over cols h
    const int y0 = blockIdx.y * 32;  // over rows o
    if (x0 >= Cc || y0 >= R) return;

    if (ty == 0) {
        int o = y0 + tx;
        float sc = 1.0f;
        if (o < R) {
            if (z == 0)                 sc = g1[o] * rsqrtf(v1[o] + 1e-5f) * (1.0f - alpha1[o]);
            else if (z == 1 || z == 2)  sc = g2[o] * rsqrtf(v2[o] + 1e-5f) * (1.0f - alpha2[o]);
            else if (z == 3)            sc = 1.0f - beta_out[o];
            else                        sc = g1[o] * rsqrtf(v1[o] + 1e-5f);
        }
        scs[tx] = sc;
    }
    __syncthreads();

    #pragma unroll
    for (int k = 0; k < 4; k++) {
        int o = y0 + ty + 8*k;
        int hh = x0 + tx;
        if (o < R && hh < Cc)
            tile[ty + 8*k][tx] = src[(size_t)o * Cc + hh] * scs[ty + 8*k];
    }
    __syncthreads();
    #pragma unroll
    for (int k = 0; k < 4; k++) {
        int hh = x0 + ty + 8*k;
        int o = y0 + tx;
        if (hh < Cc && o < R) dst[(size_t)hh * R + o] = tile[tx][ty + 8*k];
    }
}

// ---------------- xd: delayed-input gather, transposed output [c][b*TT+t] -------------
__global__ __launch_bounds__(256) void xd_kernel(const float* __restrict__ x,
                                                 const float* __restrict__ delay_raw)
{
    __shared__ float sx[TT * CC];
    __shared__ int   fli[CC];
    __shared__ float frac[CC];

    const int b   = blockIdx.x;
    const int tid = threadIdx.x;

    if (tid < CC) {
        float xr = delay_raw[tid];
        float s  = (xr >= 0.0f) ? (1.0f / (1.0f + expf(-xr)))
                                : (expf(xr) / (1.0f + expf(xr)));
        float d  = s * 30.0f;        // MAX_DELAY
        float fl = floorf(d);
        fli[tid]  = (int)fl;
        frac[tid] = d - fl;
    }
    const float* xb = x + (size_t)b * TT * CC;
    for (int i = tid; i < TT * CC; i += 256) sx[i] = xb[i];
    __syncthreads();

    for (int i = tid; i < TT * CC; i += 256) {
        int c = i / TT, t = i - c * TT;
        int i0 = t - fli[c];
        float fr = frac[c];
        float x0 = (i0 >= 0) ? sx[i0 * CC + c]       : 0.0f;
        float x1 = (i0 >= 1) ? sx[(i0 - 1) * CC + c] : 0.0f;
        g_xdT[(size_t)c * MT + b * TT + t] = (1.0f - fr) * x0 + fr * x1;
    }
}

// ---------------- P1 GEMM: 128x128, f32x2 mainloop, bf16x2 packed stores --------------
__global__ __launch_bounds__(256) void gemm_p1_kernel(const float* __restrict__ alpha1)
{
    __shared__ __align__(16) float xs[CC][128];
    __shared__ __align__(16) float ws[CC][128];
    __shared__ float sh1s[128];
    __shared__ float omas[128];

    const int tid = threadIdx.x;
    const int h0  = blockIdx.x * 128;
    const int r0  = blockIdx.y * 128;

    #pragma unroll
    for (int v = tid; v < 32 * CC; v += 256) {
        int c = v >> 5, off = v & 31;
        ((float4*)xs)[c * 32 + off] = ((const float4*)(g_xdT + (size_t)c * MT + r0))[off];
    }
    #pragma unroll
    for (int v = tid; v < 32 * CC; v += 256) {
        int c = v >> 5, off = v & 31;
        ((float4*)ws)[c * 32 + off] = ((const float4*)(g_WdT + c * H1 + h0))[off];
    }
    if (tid < 128) {
        sh1s[tid] = g_shift1[h0 + tid];
        omas[tid] = 1.0f - alpha1[h0 + tid];
    }
    __syncthreads();

    const int ty = tid >> 4;
    const int tx = tid & 15;

    uint64_t acc[8][4];
    #pragma unroll
    for (int i = 0; i < 8; i++)
        #pragma unroll
        for (int j = 0; j < 4; j++) acc[i][j] = 0ULL;

    #pragma unroll
    for (int k = 0; k < CC; k++) {
        float4 A0 = *(const float4*)&xs[k][ty * 8];
        float4 A1 = *(const float4*)&xs[k][ty * 8 + 4];
        float4 W0 = *(const float4*)&ws[k][tx * 8];
        float4 W1 = *(const float4*)&ws[k][tx * 8 + 4];
        uint64_t w01 = pack2(W0.x, W0.y);
        uint64_t w23 = pack2(W0.z, W0.w);
        uint64_t w45 = pack2(W1.x, W1.y);
        uint64_t w67 = pack2(W1.z, W1.w);
        float av[8] = {A0.x, A0.y, A0.z, A0.w, A1.x, A1.y, A1.z, A1.w};
        #pragma unroll
        for (int ii = 0; ii < 8; ii++) {
            uint64_t ad = dup2(av[ii]);
            acc[ii][0] = fma2(ad, w01, acc[ii][0]);
            acc[ii][1] = fma2(ad, w23, acc[ii][1]);
            acc[ii][2] = fma2(ad, w45, acc[ii][2]);
            acc[ii][3] = fma2(ad, w67, acc[ii][3]);
        }
    }

    uint64_t sh0 = pack2(sh1s[tx*8+0], sh1s[tx*8+1]);
    uint64_t sh1 = pack2(sh1s[tx*8+2], sh1s[tx*8+3]);
    uint64_t sh2 = pack2(sh1s[tx*8+4], sh1s[tx*8+5]);
    uint64_t sh3 = pack2(sh1s[tx*8+6], sh1s[tx*8+7]);
    float om[8];
    #pragma unroll
    for (int j = 0; j < 8; j++) om[j] = omas[tx*8+j];

    #pragma unroll
    for (int ii = 0; ii < 8; ii++) {
        int r = r0 + ty * 8 + ii;
        float2 p0 = unpack2(add2(acc[ii][0], sh0));
        float2 p1 = unpack2(add2(acc[ii][1], sh1));
        float2 p2 = unpack2(add2(acc[ii][2], sh2));
        float2 p3 = unpack2(add2(acc[ii][3], sh3));
        __nv_bfloat162 b0 = __float22bfloat162_rn(make_float2(p0.x*om[0], p0.y*om[1]));
        __nv_bfloat162 b1 = __float22bfloat162_rn(make_float2(p1.x*om[2], p1.y*om[3]));
        __nv_bfloat162 b2 = __float22bfloat162_rn(make_float2(p2.x*om[4], p2.y*om[5]));
        __nv_bfloat162 b3 = __float22bfloat162_rn(make_float2(p3.x*om[6], p3.y*om[7]));
        uint4 pk;
        pk.x = *(uint32_t*)&b0; pk.y = *(uint32_t*)&b1;
        pk.z = *(uint32_t*)&b2; pk.w = *(uint32_t*)&b3;
        *(uint4*)&g_P1h[(size_t)r * (H1/2) + (h0 + tx * 8) / 2] = pk;
    }
}

// ---------------- step kernel: 256 CTAs x 512 thr, bf16x2 P1, paired L1 neurons --------
// thread tid owns L1 neurons 2*tid, 2*tid+1  and L2 neuron tid.
#define SNN_STEP(RQ1, WQ1, ZQ1, DO_L1, DO_RO)                                              \
{                                                                                          \
    if (tid == 0) { s_cnt1[ZQ1] = 0; s_cnt2[WQ1] = 0; }                                    \
    /* L2(t): reads s1(t) buf RQ1, s2(t-1) buf ZQ1; writes s2(t) buf RQ1 */                \
    {                                                                                      \
        float u = shift2s;                                                                 \
        int n = s_cnt1[RQ1];                                                               \
        for (int j = 0; j < n; j++) u += g_W2T[s_list1[RQ1][j] * H2 + tid];                \
        int m = s_cnt2[ZQ1];                                                               \
        for (int j = 0; j < m; j++) u += g_Wr2T[s_list2[ZQ1][j] * H2 + tid];               \
        float an = rh2 * a2 + ba2 * s2;                                                    \
        float vn = al2 * v2 + u - an - s2;                                                 \
        float sn = (vn >= 1.0f) ? 1.0f : 0.0f;                                             \
        a2 = an; v2 = vn; s2 = sn;                                                         \
        if (sn != 0.0f) { int pos = atomicAdd(&s_cnt2[RQ1], 1); s_list2[RQ1][pos] = tid; } \
    }                                                                                      \
    /* L1(t+1): reads s1(t) buf RQ1, p1 (packed bf16x2 for t+1); writes buf WQ1 */         \
    if (DO_L1) {                                                                           \
        float r0 = 0.f, r1 = 0.f;                                                          \
        int n = s_cnt1[RQ1];                                                               \
        for (int j = 0; j < n; j++) {                                                      \
            float2 w = *(const float2*)(g_Wr1T + s_list1[RQ1][j] * H1 + 2 * tid);          \
            r0 += w.x; r1 += w.y;                                                          \
        }                                                                                  \
        float2 pc = __bfloat1622float2(*(const __nv_bfloat162*)&p1);                       \
        {                                                                                  \
            float an = rh1_0 * a1_0 + ba1_0 * s1_0;                                        \
            float vn = al1_0 * v1_0 + pc.x + r0 - an - s1_0;                               \
            float sn = (vn >= 1.0f) ? 1.0f : 0.0f;                                         \
            a1_0 = an; v1_0 = vn; s1_0 = sn;                                               \
            if (sn != 0.0f) { int pos = atomicAdd(&s_cnt1[WQ1], 1); s_list1[WQ1][pos] = 2*tid; } \
        }                                                                                  \
        {                                                                                  \
            float an = rh1_1 * a1_1 + ba1_1 * s1_1;                                        \
            float vn = al1_1 * v1_1 + pc.y + r1 - an - s1_1;                               \
            float sn = (vn >= 1.0f) ? 1.0f : 0.0f;                                         \
            a1_1 = an; v1_1 = vn; s1_1 = sn;                                               \
            if (sn != 0.0f) { int pos = atomicAdd(&s_cnt1[WQ1], 1); s_list1[WQ1][pos] = 2*tid+1; } \
        }                                                                                  \
    }                                                                                      \
    /* readout(t-1): reads s2(t-1) buf ZQ1 */                                              \
    if (DO_RO && tid < OO) {                                                               \
        float io = 0.f;                                                                    \
        int m = s_cnt2[ZQ1];                                                               \
        for (int j = 0; j < m; j++) io += g_WoT[s_list2[ZQ1][j] * OO + tid];               \
        vo = bo * vo + io; accv += vo;                                                     \
    }                                                                                      \
    { uint32_t q = *pfu; pfu += (H1/2);                                                    \
      __syncthreads();                                                                     \
      p1 = p2; p2 = q; }                                                                   \
}

__global__ __launch_bounds__(512, 2) void snn_kernel(
    const float* __restrict__ bn2_gamma, const float* __restrict__ bn2_beta,
    const float* __restrict__ bn2_mean,  const float* __restrict__ bn2_var,
    const float* __restrict__ alpha1, const float* __restrict__ rho1, const float* __restrict__ beta_a1,
    const float* __restrict__ alpha2, const float* __restrict__ rho2, const float* __restrict__ beta_a2,
    const float* __restrict__ beta_out,
    float* __restrict__ out)
{
    __shared__ int s_list1[3][H1];
    __shared__ int s_list2[3][H2];
    __shared__ int s_cnt1[3];
    __shared__ int s_cnt2[3];

    const int tid = threadIdx.x;
    const int b   = blockIdx.x;

    if (tid < 3) { s_cnt1[tid] = 0; s_cnt2[tid] = 0; }

    // layer-1: neurons 2*tid, 2*tid+1 (paired -> float2 const loads)
    const float2 AL1 = *(const float2*)(alpha1  + 2 * tid);
    const float2 RH1 = *(const float2*)(rho1    + 2 * tid);
    const float2 BA1 = *(const float2*)(beta_a1 + 2 * tid);
    const float al1_0 = AL1.x, al1_1 = AL1.y;
    const float rh1_0 = RH1.x, rh1_1 = RH1.y;
    const float ba1_0 = BA1.x, ba1_1 = BA1.y;
    float v1_0 = 0.f, a1_0 = 0.f, s1_0 = 0.f;
    float v1_1 = 0.f, a1_1 = 0.f, s1_1 = 0.f;

    // layer-2: neuron tid (H2 = 512)
    const float sc2     = bn2_gamma[tid] * rsqrtf(bn2_var[tid] + 1e-5f);
    const float al2     = alpha2[tid];
    const float shift2s = (1.0f - al2) * (bn2_beta[tid] - bn2_mean[tid] * sc2);
    const float rh2 = rho2[tid], ba2 = beta_a2[tid];
    float v2 = 0.f, a2 = 0.f, s2 = 0.f;

    // readout (threads 0..34)
    float vo = 0.f, accv = 0.f, bo = 0.f;
    if (tid < OO) bo = beta_out[tid];

    const uint32_t* baseu = (const uint32_t*)g_P1h + (size_t)b * TT * (H1/2) + tid;
    uint32_t p0 = baseu[0];
    uint32_t p1 = baseu[H1/2];
    uint32_t p2 = baseu[2 * (H1/2)];
    const uint32_t* pfu = baseu + 3 * (H1/2);

    __syncthreads();

    // ---- prologue: L1(0) -> buf 0 ----
    {
        float2 pc = __bfloat1622float2(*(const __nv_bfloat162*)&p0);
        {
            float an = rh1_0 * a1_0 + ba1_0 * s1_0;
            float vn = al1_0 * v1_0 + pc.x - an - s1_0;
            float sn = (vn >= 1.0f) ? 1.0f : 0.0f;
            a1_0 = an; v1_0 = vn; s1_0 = sn;
            if (sn != 0.0f) { int pos = atomicAdd(&s_cnt1[0], 1); s_list1[0][pos] = 2*tid; }
        }
        {
            float an = rh1_1 * a1_1 + ba1_1 * s1_1;
            float vn = al1_1 * v1_1 + pc.y - an - s1_1;
            float sn = (vn >= 1.0f) ? 1.0f : 0.0f;
            a1_1 = an; v1_1 = vn; s1_1 = sn;
            if (sn != 0.0f) { int pos = atomicAdd(&s_cnt1[0], 1); s_list1[0][pos] = 2*tid+1; }
        }
    }
    __syncthreads();

    // iter 0 (no readout), then 32 triples covering t=1..96, then t=97,98,99
    SNN_STEP(0, 1, 2, 1, 0)
    #pragma unroll 1
    for (int k = 0; k < 32; k++) {
        SNN_STEP(1, 2, 0, 1, 1)
        SNN_STEP(2, 0, 1, 1, 1)
        SNN_STEP(0, 1, 2, 1, 1)
    }
    SNN_STEP(1, 2, 0, 1, 1)     // t=97
    SNN_STEP(2, 0, 1, 1, 1)     // t=98
    SNN_STEP(0, 1, 2, 0, 1)     // t=99, no L1(100)

    // ---- epilogue: readout(99), s2(99) in buf 0 ----
    if (tid < OO) {
        float io = 0.f;
        int m = s_cnt2[0];
        for (int j = 0; j < m; j++) io += g_WoT[s_list2[0][j] * OO + tid];
        vo = bo * vo + io;
        accv += vo;
        out[b * OO + tid] = accv * (1.0f / (float)TT);
    }
}

// ---------------- launch ----------------
extern "C" void kernel_launch(void* const* d_in, const int* in_sizes, int n_in,
                              void* d_out, int out_size)
{
    const float* x         = (const float*)d_in[0];
    const float* W_delay   = (const float*)d_in[1];
    const float* delay_raw = (const float*)d_in[2];
    const float* W_rec1    = (const float*)d_in[3];
    const float* W2        = (const float*)d_in[4];
    const float* W_rec2    = (const float*)d_in[5];
    const float* W_out     = (const float*)d_in[6];
    const float* bn1_gamma = (const float*)d_in[7];
    const float* bn1_beta  = (const float*)d_in[8];
    const float* bn1_mean  = (const float*)d_in[9];
    const float* bn1_var   = (const float*)d_in[10];
    const float* bn2_gamma = (const float*)d_in[11];
    const float* bn2_beta  = (const float*)d_in[12];
    const float* bn2_mean  = (const float*)d_in[13];
    const float* bn2_var   = (const float*)d_in[14];
    const float* alpha1    = (const float*)d_in[15];
    const float* rho1      = (const float*)d_in[16];
    const float* beta_a1   = (const float*)d_in[17];
    const float* alpha2    = (const float*)d_in[18];
    const float* rho2      = (const float*)d_in[19];
    const float* beta_a2   = (const float*)d_in[20];
    const float* beta_out  = (const float*)d_in[21];

    dim3 pb(32, 8);
    dim3 pg(32, 32, 6);
    prep_kernel<<<pg, pb>>>(W_rec1, W2, W_rec2, W_out, W_delay,
                            bn1_gamma, bn1_beta, bn1_mean, bn1_var,
                            bn2_gamma, bn2_var,
                            alpha1, alpha2, beta_out);

    xd_kernel<<<BB, 256>>>(x, delay_raw);

    dim3 gg(H1 / 128, MT / 128);   // (8, 200)
    gemm_p1_kernel<<<gg, 256>>>(alpha1);

    snn_kernel<<<BB, 512>>>(bn2_gamma, bn2_beta, bn2_mean, bn2_var,
                            alpha1, rho1, beta_a1,
                            alpha2, rho2, beta_a2,
                            beta_out,
                            (float*)d_out);
}